// round 6
// baseline (speedup 1.0000x reference)
#include <cuda_runtime.h>
#include <cuda_fp16.h>
#include <cstdint>

#define N_NODES 100000
#define N_EDGES 1600000
#define D_FEAT  50
#define D2      25                       // half2 / float2 elements per row
#define EDGE_BLOCKS  ((N_EDGES + 255) / 256)
#define FEAT2        (N_NODES * D2)      // 2.5M half2 elements
#define FEAT_BLOCKS  ((FEAT2 + 255) / 256)
#define SCAN_BLOCKS  ((N_NODES + 1023) / 1024)   // 98

static __device__ __constant__ float TAU = 0.1f / 1.8f;   // gamma * lambda

// ---------------- scratch (device globals; allocation is forbidden) --------
struct Zeroed {                      // zeroed by ONE cudaMemsetAsync per call
    float outdeg[N_NODES];           // weighted out-degree, self-loop added as +1 later
    float indeg [N_NODES];
    int   cnt   [N_NODES];           // edge count by dst (no self-loop)
    unsigned long long tile[SCAN_BLOCKS];   // {flag<<32 | inclusive prefix}
};
__device__ Zeroed  g_z;
__device__ int2    g_rows  [N_NODES];    // {start, cnt}
__device__ int     g_cursor[N_NODES];
__device__ float   g_isqo  [N_NODES];
__device__ float   g_isqi  [N_NODES];
__device__ float   g_ws    [N_NODES];    // self-loop weight = isqo*isqi
__device__ float2  g_edge  [N_EDGES];    // {src (bits), normalized w}
__device__ __half2 g_feath [FEAT2];      // fp16 copy of feat (gather source, iter 1)
__device__ __half2 g_x1h   [FEAT2];
__device__ __half2 g_x2h   [FEAT2];

// ---------------- pass 1: degrees + feat->fp16 (disjoint block ranges) -----
__global__ void __launch_bounds__(256)
k_deg_feat(const float* __restrict__ ew, const int* __restrict__ src,
           const int* __restrict__ dst, const float* __restrict__ feat) {
    if (blockIdx.x < EDGE_BLOCKS) {
        int e = blockIdx.x * 256 + threadIdx.x;
        if (e < N_EDGES) {
            float w = ew[e];
            int s = src[e], d = dst[e];
            atomicAdd(&g_z.outdeg[s], w);
            atomicAdd(&g_z.indeg [d], w);
            atomicAdd(&g_z.cnt   [d], 1);
        }
    } else {
        int j = (blockIdx.x - EDGE_BLOCKS) * 256 + threadIdx.x;
        if (j < FEAT2) {
            float2 f = reinterpret_cast<const float2*>(feat)[j];
            g_feath[j] = __floats2half2_rn(f.x, f.y);
        }
    }
}

// ---------------- pass 2: single-kernel chained scan + node prep -----------
// 98 blocks of 1024 (<148 SMs -> all resident, chain cannot deadlock).
__global__ void __launch_bounds__(1024)
k_scanall() {
    int b = blockIdx.x, t = threadIdx.x;
    int i = b * 1024 + t;
    int v = (i < N_NODES) ? g_z.cnt[i] : 0;

    // warp-level inclusive scan
    int lane = t & 31, w = t >> 5;
    int x = v;
    #pragma unroll
    for (int o = 1; o < 32; o <<= 1) {
        int y = __shfl_up_sync(0xffffffffu, x, o);
        if (lane >= o) x += y;
    }
    __shared__ int wsum[32];
    if (lane == 31) wsum[w] = x;
    __syncthreads();
    if (w == 0) {
        int s = wsum[lane];
        #pragma unroll
        for (int o = 1; o < 32; o <<= 1) {
            int y = __shfl_up_sync(0xffffffffu, s, o);
            if (lane >= o) s += y;
        }
        wsum[lane] = s;
    }
    __syncthreads();
    int incl = x + (w ? wsum[w - 1] : 0);
    int blocktotal = wsum[31];

    // chained lookback: packed {ready<<32 | inclusive-prefix}
    __shared__ int s_pref;
    if (t == 0) {
        int pref = 0;
        if (b > 0) {
            unsigned long long u;
            do { u = atomicAdd(&g_z.tile[b - 1], 0ULL); } while (!(u >> 32));
            pref = (int)(u & 0xffffffffULL);
        }
        atomicExch(&g_z.tile[b], (1ULL << 32) | (unsigned)(pref + blocktotal));
        s_pref = pref;
    }
    __syncthreads();

    if (i < N_NODES) {
        int start = s_pref + incl - v;      // exclusive prefix
        g_rows[i]   = make_int2(start, v);
        g_cursor[i] = start;
        float io = rsqrtf(g_z.outdeg[i] + 1.0f);   // +1 = self-loop weight
        float ii = rsqrtf(g_z.indeg [i] + 1.0f);
        g_isqo[i] = io;
        g_isqi[i] = ii;
        g_ws  [i] = io * ii;
    }
}

// ---------------- pass 3: scatter edges into CSR-by-dst --------------------
__global__ void __launch_bounds__(256)
k_scatter(const float* __restrict__ ew, const int* __restrict__ src,
          const int* __restrict__ dst) {
    int e = blockIdx.x * 256 + threadIdx.x;
    if (e >= N_EDGES) return;
    int s = src[e], d = dst[e];
    float w = ew[e] * g_isqo[s] * g_isqi[d];
    int pos = atomicAdd(&g_cursor[d], 1);
    g_edge[pos] = make_float2(__int_as_float(s), w);
}

// ---------------- fused SpMM + proximal: warp per dst node -----------------
template <bool LAST>
__global__ void __launch_bounds__(256)
k_spmm_prox(const __half2* __restrict__ xin,
            const float* __restrict__ feat,
            void* __restrict__ xout) {
    int warp = (blockIdx.x * blockDim.x + threadIdx.x) >> 5;
    int lane = threadIdx.x & 31;
    if (warp >= N_NODES) return;
    const int  i   = warp;
    const int2 row = g_rows[i];                 // {start, cnt}, uniform load
    const float ws = g_ws[i];
    const bool act = lane < D2;

    float2 acc = make_float2(0.f, 0.f);
    if (act) {
        float2 xv = __half22float2(xin[i * D2 + lane]);
        acc.x = ws * xv.x;
        acc.y = ws * xv.y;
    }

    const float2* __restrict__ ep = g_edge + row.x;
    const int cnt = row.y;
    int e = 0;
    // 4-edge pipeline: metas (uniform 8B) issue ahead of dependent gathers
    for (; e + 4 <= cnt; e += 4) {
        float2 m0 = ep[e], m1 = ep[e + 1], m2 = ep[e + 2], m3 = ep[e + 3];
        if (act) {
            float2 v0 = __half22float2(xin[__float_as_int(m0.x) * D2 + lane]);
            float2 v1 = __half22float2(xin[__float_as_int(m1.x) * D2 + lane]);
            float2 v2 = __half22float2(xin[__float_as_int(m2.x) * D2 + lane]);
            float2 v3 = __half22float2(xin[__float_as_int(m3.x) * D2 + lane]);
            acc.x = fmaf(m0.y, v0.x, acc.x);  acc.y = fmaf(m0.y, v0.y, acc.y);
            acc.x = fmaf(m1.y, v1.x, acc.x);  acc.y = fmaf(m1.y, v1.y, acc.y);
            acc.x = fmaf(m2.y, v2.x, acc.x);  acc.y = fmaf(m2.y, v2.y, acc.y);
            acc.x = fmaf(m3.y, v3.x, acc.x);  acc.y = fmaf(m3.y, v3.y, acc.y);
        }
    }
    for (; e < cnt; e++) {
        float2 m0 = ep[e];
        if (act) {
            float2 v0 = __half22float2(xin[__float_as_int(m0.x) * D2 + lane]);
            acc.x = fmaf(m0.y, v0.x, acc.x);
            acc.y = fmaf(m0.y, v0.y, acc.y);
        }
    }

    // proximal L2,1 on (agg - feat); y == agg since gamma*2*(1-lam) == 1
    float2 f = act ? reinterpret_cast<const float2*>(feat)[i * D2 + lane]
                   : make_float2(0.f, 0.f);
    float dx = acc.x - f.x;
    float dy = acc.y - f.y;
    float sq = act ? (dx * dx + dy * dy) : 0.f;
    #pragma unroll
    for (int o = 16; o; o >>= 1)
        sq += __shfl_xor_sync(0xffffffffu, sq, o);
    float nrm = sqrtf(sq);
    float scale = (nrm > 0.f) ? fmaxf(nrm - TAU, 0.f) / nrm : 0.f;

    if (act) {
        float ox = f.x + scale * dx;
        float oy = f.y + scale * dy;
        if (LAST) {
            reinterpret_cast<float2*>(xout)[i * D2 + lane] = make_float2(ox, oy);
        } else {
            reinterpret_cast<__half2*>(xout)[i * D2 + lane] = __floats2half2_rn(ox, oy);
        }
    }
}

// ---------------- launch ----------------------------------------------------
extern "C" void kernel_launch(void* const* d_in, const int* in_sizes, int n_in,
                              void* d_out, int out_size) {
    const float* feat = (const float*)d_in[0];
    const float* ew   = (const float*)d_in[1];
    const int*   src  = (const int*)d_in[2];
    const int*   dst  = (const int*)d_in[3];

    void *zptr, *fh, *x1, *x2;
    cudaGetSymbolAddress(&zptr, g_z);
    cudaGetSymbolAddress(&fh,   g_feath);
    cudaGetSymbolAddress(&x1,   g_x1h);
    cudaGetSymbolAddress(&x2,   g_x2h);

    cudaMemsetAsync(zptr, 0, sizeof(Zeroed));                       // node 1
    k_deg_feat<<<EDGE_BLOCKS + FEAT_BLOCKS, 256>>>(ew, src, dst, feat); // 2
    k_scanall <<<SCAN_BLOCKS, 1024>>>();                            // 3
    k_scatter <<<EDGE_BLOCKS, 256>>>(ew, src, dst);                 // 4

    const int spmmBlocks = (N_NODES * 32 + 255) / 256;              // warp/node
    k_spmm_prox<false><<<spmmBlocks, 256>>>((const __half2*)fh, feat, x1);
    k_spmm_prox<false><<<spmmBlocks, 256>>>((const __half2*)x1, feat, x2);
    k_spmm_prox<true ><<<spmmBlocks, 256>>>((const __half2*)x2, feat, d_out);
}

// round 7
// speedup vs baseline: 1.0257x; 1.0257x over previous
#include <cuda_runtime.h>
#include <cuda_fp16.h>
#include <cstdint>

#define N_NODES 100000
#define N_EDGES 1600000
#define D_FEAT  50
#define PAD2    32                        // half2 per padded row (64 halves = 128B)
#define PADU2   16                        // uint2 (4 halves) per padded row
#define EDGE_BLOCKS  ((N_EDGES + 255) / 256)
#define CONV2        (N_NODES * PAD2)     // 3.2M half2 slots
#define CONV_BLOCKS  ((CONV2 + 255) / 256)
#define SCAN_BLOCKS  ((N_NODES + 1023) / 1024)   // 98

static __device__ __constant__ float TAU = 0.1f / 1.8f;   // gamma * lambda

// ---------------- scratch (device globals; allocation is forbidden) --------
struct Zeroed {                       // zeroed by ONE cudaMemsetAsync
    float outdeg[N_NODES];
    float indeg [N_NODES];
    int   cnt   [N_NODES];
    unsigned long long tile[SCAN_BLOCKS];   // {flag<<32 | inclusive prefix}
};
__device__ Zeroed  g_z;
__device__ int2    g_rows  [N_NODES];     // {start, cnt}
__device__ int     g_cursor[N_NODES];
__device__ float   g_isqo  [N_NODES];
__device__ float   g_isqi  [N_NODES];
__device__ float   g_ws    [N_NODES];     // self-loop weight
__device__ float2  g_edge  [N_EDGES];     // {src (bits), normalized w}
__device__ __half2 g_feath [CONV2];       // fp16 feat, 128B-padded rows
__device__ __half2 g_x1h   [CONV2];
__device__ __half2 g_x2h   [CONV2];

// ---------------- pass 1: degrees + feat->fp16-padded (disjoint ranges) ----
__global__ void __launch_bounds__(256)
k_deg_feat(const float* __restrict__ ew, const int* __restrict__ src,
           const int* __restrict__ dst, const float* __restrict__ feat) {
    if (blockIdx.x < EDGE_BLOCKS) {
        int e = blockIdx.x * 256 + threadIdx.x;
        if (e < N_EDGES) {
            float w = ew[e];
            int s = src[e], d = dst[e];
            atomicAdd(&g_z.outdeg[s], w);
            atomicAdd(&g_z.indeg [d], w);
            atomicAdd(&g_z.cnt   [d], 1);
        }
    } else {
        int j = (blockIdx.x - EDGE_BLOCKS) * 256 + threadIdx.x;
        if (j < CONV2) {
            int row = j >> 5, c = j & 31;
            __half2 h = __floats2half2_rn(0.f, 0.f);
            if (c < 25) {
                float2 f = reinterpret_cast<const float2*>(feat)[row * 25 + c];
                h = __floats2half2_rn(f.x, f.y);
            }
            g_feath[j] = h;
        }
    }
}

// ---------------- pass 2: chained-lookback scan + node prep ----------------
__global__ void __launch_bounds__(1024)
k_scanall() {
    int b = blockIdx.x, t = threadIdx.x;
    int i = b * 1024 + t;
    int v = (i < N_NODES) ? g_z.cnt[i] : 0;

    int lane = t & 31, w = t >> 5;
    int x = v;
    #pragma unroll
    for (int o = 1; o < 32; o <<= 1) {
        int y = __shfl_up_sync(0xffffffffu, x, o);
        if (lane >= o) x += y;
    }
    __shared__ int wsum[32];
    if (lane == 31) wsum[w] = x;
    __syncthreads();
    if (w == 0) {
        int s = wsum[lane];
        #pragma unroll
        for (int o = 1; o < 32; o <<= 1) {
            int y = __shfl_up_sync(0xffffffffu, s, o);
            if (lane >= o) s += y;
        }
        wsum[lane] = s;
    }
    __syncthreads();
    int incl = x + (w ? wsum[w - 1] : 0);
    int blocktotal = wsum[31];

    __shared__ int s_pref;
    if (t == 0) {
        int pref = 0;
        if (b > 0) {
            unsigned long long u;
            do { u = atomicAdd(&g_z.tile[b - 1], 0ULL); } while (!(u >> 32));
            pref = (int)(u & 0xffffffffULL);
        }
        atomicExch(&g_z.tile[b], (1ULL << 32) | (unsigned)(pref + blocktotal));
        s_pref = pref;
    }
    __syncthreads();

    if (i < N_NODES) {
        int start = s_pref + incl - v;
        g_rows[i]   = make_int2(start, v);
        g_cursor[i] = start;
        float io = rsqrtf(g_z.outdeg[i] + 1.0f);   // +1 = self-loop
        float ii = rsqrtf(g_z.indeg [i] + 1.0f);
        g_isqo[i] = io;
        g_isqi[i] = ii;
        g_ws  [i] = io * ii;
    }
}

// ---------------- pass 3: scatter edges into CSR-by-dst --------------------
__global__ void __launch_bounds__(256)
k_scatter(const float* __restrict__ ew, const int* __restrict__ src,
          const int* __restrict__ dst) {
    int e = blockIdx.x * 256 + threadIdx.x;
    if (e >= N_EDGES) return;
    int s = src[e], d = dst[e];
    float w = ew[e] * g_isqo[s] * g_isqi[d];
    int pos = atomicAdd(&g_cursor[d], 1);
    g_edge[pos] = make_float2(__int_as_float(s), w);
}

// ---------------- fused SpMM + prox: warp/node, 2 edges per warp-instr -----
__device__ __forceinline__ void fma4_h(float4& acc, float w, uint2 r) {
    float2 f0 = __half22float2(*reinterpret_cast<__half2*>(&r.x));
    float2 f1 = __half22float2(*reinterpret_cast<__half2*>(&r.y));
    acc.x = fmaf(w, f0.x, acc.x);
    acc.y = fmaf(w, f0.y, acc.y);
    acc.z = fmaf(w, f1.x, acc.z);
    acc.w = fmaf(w, f1.y, acc.w);
}

template <bool LAST>
__global__ void __launch_bounds__(256)
k_spmm_prox(const uint2* __restrict__ xin,     // padded fp16 rows, 16 uint2 each
            const float* __restrict__ feat,
            void* __restrict__ xout) {
    int warp = (blockIdx.x * blockDim.x + threadIdx.x) >> 5;
    int lane = threadIdx.x & 31;
    if (warp >= N_NODES) return;
    const int  i    = warp;
    const int  half = lane >> 4;            // 0: even edge, 1: odd edge
    const int  l16  = lane & 15;
    const int2 row  = g_rows[i];
    const float ws  = g_ws[i];

    float4 acc = make_float4(0.f, 0.f, 0.f, 0.f);

    // self-loop (lower half only; upper half FMAs by 0)
    {
        uint2 rs = xin[i * PADU2 + l16];
        fma4_h(acc, half ? 0.f : ws, rs);
    }

    const float2* __restrict__ ep = g_edge + row.x;
    const int cnt = row.y;
    int e = 0;
    for (; e + 4 <= cnt; e += 4) {          // 2 pairs in flight
        float2 mA = ep[e + half];
        float2 mB = ep[e + 2 + half];
        uint2 rA = xin[__float_as_int(mA.x) * PADU2 + l16];
        uint2 rB = xin[__float_as_int(mB.x) * PADU2 + l16];
        fma4_h(acc, mA.y, rA);
        fma4_h(acc, mB.y, rB);
    }
    if (e + 2 <= cnt) {
        float2 m = ep[e + half];
        uint2 r = xin[__float_as_int(m.x) * PADU2 + l16];
        fma4_h(acc, m.y, r);
        e += 2;
    }
    if (e < cnt) {                          // odd tail: broadcast, hi half ×0
        float2 m = ep[e];
        uint2 r = xin[__float_as_int(m.x) * PADU2 + l16];
        fma4_h(acc, half ? 0.f : m.y, r);
    }

    // combine the two edge-halves (each lane pair holds same feature slice)
    acc.x += __shfl_xor_sync(0xffffffffu, acc.x, 16);
    acc.y += __shfl_xor_sync(0xffffffffu, acc.y, 16);
    acc.z += __shfl_xor_sync(0xffffffffu, acc.z, 16);
    acc.w += __shfl_xor_sync(0xffffffffu, acc.w, 16);

    // proximal L2,1 on (agg - feat); lane's features: [4*l16, 4*l16+4)
    const float2* fp = reinterpret_cast<const float2*>(feat) + i * 25;
    float2 fa = make_float2(0.f, 0.f), fb = make_float2(0.f, 0.f);
    int c = 4 * l16;
    if (c     < 50) fa = fp[2 * l16];
    if (c + 2 < 50) fb = fp[2 * l16 + 1];

    float dx0 = acc.x - fa.x, dx1 = acc.y - fa.y;
    float dx2 = acc.z - fb.x, dx3 = acc.w - fb.y;
    float sq = dx0 * dx0 + dx1 * dx1 + dx2 * dx2 + dx3 * dx3;
    #pragma unroll
    for (int o = 8; o; o >>= 1)
        sq += __shfl_xor_sync(0xffffffffu, sq, o);
    float nrm = sqrtf(sq);
    float scale = (nrm > 0.f) ? fmaxf(nrm - TAU, 0.f) / nrm : 0.f;

    float o0 = fa.x + scale * dx0, o1 = fa.y + scale * dx1;
    float o2 = fb.x + scale * dx2, o3 = fb.y + scale * dx3;

    if (half == 0) {
        if (LAST) {
            float2* op = reinterpret_cast<float2*>((float*)xout + i * 50);
            if (c     < 50) op[2 * l16]     = make_float2(o0, o1);
            if (c + 2 < 50) op[2 * l16 + 1] = make_float2(o2, o3);
        } else {
            uint2 h;
            __half2 h0 = __floats2half2_rn(o0, o1);
            __half2 h1 = __floats2half2_rn(o2, o3);
            h.x = *reinterpret_cast<uint32_t*>(&h0);
            h.y = *reinterpret_cast<uint32_t*>(&h1);
            reinterpret_cast<uint2*>(xout)[i * PADU2 + l16] = h;
        }
    }
}

// ---------------- launch ----------------------------------------------------
extern "C" void kernel_launch(void* const* d_in, const int* in_sizes, int n_in,
                              void* d_out, int out_size) {
    const float* feat = (const float*)d_in[0];
    const float* ew   = (const float*)d_in[1];
    const int*   src  = (const int*)d_in[2];
    const int*   dst  = (const int*)d_in[3];

    void *zptr, *fh, *x1, *x2;
    cudaGetSymbolAddress(&zptr, g_z);
    cudaGetSymbolAddress(&fh,   g_feath);
    cudaGetSymbolAddress(&x1,   g_x1h);
    cudaGetSymbolAddress(&x2,   g_x2h);

    cudaMemsetAsync(zptr, 0, sizeof(Zeroed));
    k_deg_feat<<<EDGE_BLOCKS + CONV_BLOCKS, 256>>>(ew, src, dst, feat);
    k_scanall <<<SCAN_BLOCKS, 1024>>>();
    k_scatter <<<EDGE_BLOCKS, 256>>>(ew, src, dst);

    const int spmmBlocks = (N_NODES * 32 + 255) / 256;   // warp per node
    k_spmm_prox<false><<<spmmBlocks, 256>>>((const uint2*)fh, feat, x1);
    k_spmm_prox<false><<<spmmBlocks, 256>>>((const uint2*)x1, feat, x2);
    k_spmm_prox<true ><<<spmmBlocks, 256>>>((const uint2*)x2, feat, d_out);
}